// round 1
// baseline (speedup 1.0000x reference)
#include <cuda_runtime.h>
#include <math.h>

#define NLAT 128
#define NLON 256
#define LMAX 50
#define MMAX 50
#define NPTS 2048
#define NB   2
#define MG   (NLAT*NLON)
#define PI_F 3.14159265358979323846f

// scratch (device globals; no allocation allowed)
__device__ float4 g_pts [2][NB][NPTS];          // theta, phi, theta^2+phi^2, r
__device__ float  g_grid[2][NB][MG];            // interpolated lat/lon grids
__device__ float  g_pctw[MMAX][LMAX][NLAT];     // legendre * quadrature weight
__device__ float  g_rexf[2][NB][NLAT][MMAX];    // Re(rfft) * 2pi/NLON

// ---------------------------------------------------------------------------
// Legendre * Clenshaw-Curtis weight table. grid=(MMAX blocks), block=(NLAT thr)
// ---------------------------------------------------------------------------
__global__ void k_pctw() {
    int m = blockIdx.x;
    int k = threadIdx.x;
    float theta = PI_F * (float)k / (float)(NLAT - 1);
    float cost  = cosf(theta);
    float sint  = sqrtf(fmaxf(1.0f - cost * cost, 0.0f));
    // Clenshaw-Curtis weight (Nn=127 odd -> b=2 always)
    float v = 0.0f;
    for (int j = 1; j <= (NLAT - 1) / 2; ++j)
        v += 2.0f * cosf(2.0f * (float)j * theta) / (4.0f * (float)j * (float)j - 1.0f);
    float w = (2.0f / (float)(NLAT - 1)) * (1.0f - v);
    if (k == 0 || k == NLAT - 1) w *= 0.5f;
    // P_m^m chain
    float pmm = sqrtf(1.0f / (4.0f * PI_F));
    for (int mm = 1; mm <= m; ++mm)
        pmm = -pmm * sqrtf((2.0f * mm + 1.0f) / (2.0f * mm)) * sint;
    for (int l = 0; l < m; ++l) g_pctw[m][l][k] = 0.0f;
    g_pctw[m][m][k] = pmm * w;
    if (m + 1 < LMAX) {
        float plm2 = pmm;
        float plm1 = sqrtf(2.0f * m + 3.0f) * cost * pmm;
        g_pctw[m][m + 1][k] = plm1 * w;
        for (int l = m + 2; l < LMAX; ++l) {
            float fl = (float)l;
            float fm = (float)m;
            float a = sqrtf((4.0f * fl * fl - 1.0f) / (fl * fl - fm * fm));
            float b = sqrtf(((2.0f * fl + 1.0f) * (fl - 1.0f + fm) * (fl - 1.0f - fm)) /
                            ((2.0f * fl - 3.0f) * (fl * fl - fm * fm)));
            float pl = a * cost * plm1 - b * plm2;
            g_pctw[m][l][k] = pl * w;
            plm2 = plm1; plm1 = pl;
        }
    }
}

// ---------------------------------------------------------------------------
// cartesian -> spherical for all points of pred & target
// ---------------------------------------------------------------------------
__global__ void k_sph(const float* __restrict__ pred, const float* __restrict__ tgt) {
    int i = blockIdx.x * blockDim.x + threadIdx.x;
    if (i >= 2 * NB * NPTS) return;
    int t   = i / (NB * NPTS);
    int rem = i - t * (NB * NPTS);
    const float* s = (t ? tgt : pred) + 3 * rem;
    float x = s[0], y = s[1], z = s[2];
    float r   = sqrtf(x * x + y * y + z * z);
    float pn1 = sqrtf(y * y + z * z);
    float th  = acosf(fminf(fmaxf(x / r,   -1.0f), 1.0f));
    float a   = acosf(fminf(fmaxf(y / pn1, -1.0f), 1.0f));
    float ph  = (z < 0.0f) ? (2.0f * PI_F - a) : a;
    ph -= PI_F;   // sph[...,1] -= pi
    float4 o;
    o.x = th; o.y = ph; o.z = th * th + ph * ph; o.w = r;
    ((float4*)g_pts)[i] = o;
}

// ---------------------------------------------------------------------------
// 3-NN distance-weighted interpolation onto the grid.
// grid = (32, 4): blockIdx.y = tensor*2+batch; 256 threads x 4 grid pts each.
// ---------------------------------------------------------------------------
__global__ void __launch_bounds__(256) k_interp() {
    __shared__ float4 sp[NPTS];
    int t   = blockIdx.y >> 1;
    int b   = blockIdx.y & 1;
    int tid = threadIdx.x;
    const float4* gp = g_pts[t][b];
    for (int i = tid; i < NPTS; i += 256) sp[i] = gp[i];
    __syncthreads();

    float g0p[4], g1p[4], d0[4], d1[4], d2[4];
    int   i0[4], i1[4], i2[4];
    int mbase = blockIdx.x * 1024 + tid;
#pragma unroll
    for (int j = 0; j < 4; ++j) {
        int m = mbase + j * 256;
        float th = (float)(m >> 8)            * (PI_F / NLAT);
        float ph = (float)((m & 255) - NLAT)  * (PI_F / NLAT);
        g0p[j] = -2.0f * th;
        g1p[j] = -2.0f * ph;
        d0[j] = d1[j] = d2[j] = 3.4e38f;
        i0[j] = i1[j] = i2[j] = 0;
    }

#pragma unroll 2
    for (int n = 0; n < NPTS; ++n) {
        float4 p = sp[n];
#pragma unroll
        for (int j = 0; j < 4; ++j) {
            // ||g-s||^2 minus constant ||g||^2 (monotone-equivalent for top-3)
            float d = fmaf(g0p[j], p.x, fmaf(g1p[j], p.y, p.z));
            if (d < d2[j]) {
                if (d < d1[j]) {
                    d2[j] = d1[j]; i2[j] = i1[j];
                    if (d < d0[j]) { d1[j] = d0[j]; i1[j] = i0[j]; d0[j] = d; i0[j] = n; }
                    else           { d1[j] = d;     i1[j] = n; }
                } else { d2[j] = d; i2[j] = n; }
            }
        }
    }

#pragma unroll
    for (int j = 0; j < 4; ++j) {
        int m = mbase + j * 256;
        float th = (float)(m >> 8)           * (PI_F / NLAT);
        float ph = (float)((m & 255) - NLAT) * (PI_F / NLAT);
        float4 q0 = sp[i0[j]], q1 = sp[i1[j]], q2 = sp[i2[j]];
        float dx, dy;
        dx = th - q0.x; dy = ph - q0.y; float e0 = dx * dx + dy * dy;
        dx = th - q1.x; dy = ph - q1.y; float e1 = dx * dx + dy * dy;
        dx = th - q2.x; dy = ph - q2.y; float e2 = dx * dx + dy * dy;
        float s = e0 + e1 + e2;
        // w_k = d_k / sum(d) (as in source): val = sum(f_k * d_k) / sum(d)
        float val = (e0 * q0.w + e1 * q1.w + e2 * q2.w) / s;
        g_grid[t][b][m] = val;
    }
}

// ---------------------------------------------------------------------------
// Re(rfft) * (2pi/NLON), first MMAX modes. one block per (t,b,k) row.
// ---------------------------------------------------------------------------
__global__ void __launch_bounds__(64) k_rexf() {
    __shared__ float row[NLON];
    __shared__ float ctab[NLON];
    int id  = blockIdx.x;                // t*(NB*NLAT) + b*NLAT + k
    int t   = id / (NB * NLAT);
    int rem = id % (NB * NLAT);
    int b   = rem / NLAT;
    int k   = rem % NLAT;
    int tid = threadIdx.x;
    for (int i = tid; i < NLON; i += 64) {
        row[i]  = g_grid[t][b][k * NLON + i];
        ctab[i] = cosf((2.0f * PI_F / NLON) * (float)i);
    }
    __syncthreads();
    if (tid < MMAX) {
        int m = tid;
        float acc = 0.0f;
        for (int n = 0; n < NLON; ++n)
            acc = fmaf(row[n], ctab[(m * n) & (NLON - 1)], acc);
        g_rexf[t][b][k][m] = acc * (2.0f * PI_F / NLON);
    }
}

// ---------------------------------------------------------------------------
// coeffs (Legendre contraction) + weighted loss, single block.
// ---------------------------------------------------------------------------
__global__ void __launch_bounds__(1024) k_loss(float* __restrict__ out) {
    __shared__ float red[32];
    int tid = threadIdx.x;
    float acc = 0.0f;
    for (int idx = tid; idx < NB * LMAX * MMAX; idx += 1024) {
        int b  = idx / (LMAX * MMAX);
        int r2 = idx % (LMAX * MMAX);
        int l  = r2 / MMAX;
        int m  = r2 % MMAX;
        const float* pw = g_pctw[m][l];
        const float* xp = &g_rexf[0][b][0][m];
        const float* xt = &g_rexf[1][b][0][m];
        float pc = 0.0f, tc = 0.0f;
        for (int k = 0; k < NLAT; ++k) {
            float w = pw[k];
            pc = fmaf(xp[k * MMAX], w, pc);
            tc = fmaf(xt[k * MMAX], w, tc);
        }
        float d = pc - tc;
        float q = (float)(49 - l);
        acc += d * d * expf(-q * q / 5000.0f);
    }
    for (int o = 16; o > 0; o >>= 1) acc += __shfl_down_sync(0xffffffffu, acc, o);
    if ((tid & 31) == 0) red[tid >> 5] = acc;
    __syncthreads();
    if (tid < 32) {
        float v = red[tid];
        for (int o = 16; o > 0; o >>= 1) v += __shfl_down_sync(0xffffffffu, v, o);
        if (tid == 0) out[0] = v / (float)NB;
    }
}

extern "C" void kernel_launch(void* const* d_in, const int* in_sizes, int n_in,
                              void* d_out, int out_size) {
    const float* pred = (const float*)d_in[0];
    const float* tgt  = (const float*)d_in[1];
    k_pctw<<<MMAX, NLAT>>>();
    k_sph<<<(2 * NB * NPTS + 255) / 256, 256>>>(pred, tgt);
    dim3 gi(MG / 1024, 4);
    k_interp<<<gi, 256>>>();
    k_rexf<<<2 * NB * NLAT, 64>>>();
    k_loss<<<1, 1024>>>((float*)d_out);
}

// round 2
// speedup vs baseline: 7.6332x; 7.6332x over previous
#include <cuda_runtime.h>
#include <math.h>

#define NLAT 128
#define NLON 256
#define LMAX 50
#define MMAX 50
#define NPTS 2048
#define NB   2
#define MG   (NLAT*NLON)
#define NBT  32
#define NBP  64
#define NBINS (NBT*NBP)
#define PI_F 3.14159265358979323846f
#define H_BIN (PI_F/32.0f)
#define INVH  (32.0f/PI_F)

// scratch (device globals; no allocation allowed)
__device__ float4 g_pts [4][NPTS];            // theta, phi, r, pad   (combo = t*2+b)
__device__ float4 g_sorted[4][NPTS];          // bin-sorted copy
__device__ int    g_binstart[4][NBINS + 1];
__device__ float  g_grid[4][MG];              // interpolated grids
__device__ float  g_pctw[MMAX][LMAX][NLAT];   // legendre * quadrature weight
__device__ float  g_rexf[4][MMAX][NLAT];      // Re(rfft)*2pi/NLON, m-major
__device__ float  g_part[NB*LMAX*MMAX];       // per-(b,l,m) weighted sq diffs

__device__ __forceinline__ int bin_of(float th, float ph) {
    int bt = (int)(th * INVH);
    int bp = (int)((ph + PI_F) * INVH);
    bt = min(max(bt, 0), NBT - 1);
    bp = min(max(bp, 0), NBP - 1);
    return bt * NBP + bp;
}

// ---------------------------------------------------------------------------
// Legendre * Clenshaw-Curtis weight table. grid=(MMAX blocks), block=(NLAT thr)
// ---------------------------------------------------------------------------
__global__ void k_pctw() {
    int m = blockIdx.x;
    int k = threadIdx.x;
    float theta = PI_F * (float)k / (float)(NLAT - 1);
    float cost  = cosf(theta);
    float sint  = sqrtf(fmaxf(1.0f - cost * cost, 0.0f));
    float v = 0.0f;
    for (int j = 1; j <= (NLAT - 1) / 2; ++j)
        v += 2.0f * cosf(2.0f * (float)j * theta) / (4.0f * (float)j * (float)j - 1.0f);
    float w = (2.0f / (float)(NLAT - 1)) * (1.0f - v);
    if (k == 0 || k == NLAT - 1) w *= 0.5f;
    float pmm = sqrtf(1.0f / (4.0f * PI_F));
    for (int mm = 1; mm <= m; ++mm)
        pmm = -pmm * sqrtf((2.0f * mm + 1.0f) / (2.0f * mm)) * sint;
    for (int l = 0; l < m; ++l) g_pctw[m][l][k] = 0.0f;
    g_pctw[m][m][k] = pmm * w;
    if (m + 1 < LMAX) {
        float plm2 = pmm;
        float plm1 = sqrtf(2.0f * m + 3.0f) * cost * pmm;
        g_pctw[m][m + 1][k] = plm1 * w;
        for (int l = m + 2; l < LMAX; ++l) {
            float fl = (float)l, fm = (float)m;
            float a = sqrtf((4.0f * fl * fl - 1.0f) / (fl * fl - fm * fm));
            float b = sqrtf(((2.0f * fl + 1.0f) * (fl - 1.0f + fm) * (fl - 1.0f - fm)) /
                            ((2.0f * fl - 3.0f) * (fl * fl - fm * fm)));
            float pl = a * cost * plm1 - b * plm2;
            g_pctw[m][l][k] = pl * w;
            plm2 = plm1; plm1 = pl;
        }
    }
}

// ---------------------------------------------------------------------------
// cartesian -> spherical
// ---------------------------------------------------------------------------
__global__ void k_sph(const float* __restrict__ pred, const float* __restrict__ tgt) {
    int i = blockIdx.x * blockDim.x + threadIdx.x;
    if (i >= 4 * NPTS) return;
    int combo = i >> 11;
    int pt    = i & (NPTS - 1);
    int t     = combo >> 1;
    int b     = combo & 1;
    const float* s = (t ? tgt : pred) + 3 * (b * NPTS + pt);
    float x = s[0], y = s[1], z = s[2];
    float r   = sqrtf(x * x + y * y + z * z);
    float pn1 = sqrtf(y * y + z * z);
    float th  = acosf(fminf(fmaxf(x / r,   -1.0f), 1.0f));
    float a   = acosf(fminf(fmaxf(y / pn1, -1.0f), 1.0f));
    float ph  = ((z < 0.0f) ? (2.0f * PI_F - a) : a) - PI_F;
    float4 o; o.x = th; o.y = ph; o.z = r; o.w = 0.0f;
    g_pts[combo][pt] = o;
}

// ---------------------------------------------------------------------------
// counting-sort points into bins. grid=4 blocks (one per combo), 256 threads.
// ---------------------------------------------------------------------------
__global__ void __launch_bounds__(256) k_bin() {
    __shared__ int cnt[NBINS];
    __shared__ int off[NBINS];
    __shared__ int wsum[8];
    int cb  = blockIdx.x;
    int tid = threadIdx.x;
    for (int i = tid; i < NBINS; i += 256) cnt[i] = 0;
    __syncthreads();
    for (int i = tid; i < NPTS; i += 256) {
        float4 p = g_pts[cb][i];
        atomicAdd(&cnt[bin_of(p.x, p.y)], 1);
    }
    __syncthreads();
    // exclusive scan over 2048 bins (8 per thread)
    int base = tid * 8;
    int local[8]; int s = 0;
#pragma unroll
    for (int j = 0; j < 8; ++j) { local[j] = s; s += cnt[base + j]; }
    int lane = tid & 31, wrp = tid >> 5;
    int v = s;
#pragma unroll
    for (int o = 1; o < 32; o <<= 1) {
        int u = __shfl_up_sync(0xffffffffu, v, o);
        if (lane >= o) v += u;
    }
    if (lane == 31) wsum[wrp] = v;
    __syncthreads();
    if (tid == 0) { int a = 0; for (int j = 0; j < 8; ++j) { int x = wsum[j]; wsum[j] = a; a += x; } }
    __syncthreads();
    int excl = v - s + wsum[wrp];
#pragma unroll
    for (int j = 0; j < 8; ++j) off[base + j] = excl + local[j];
    __syncthreads();
    for (int i = tid; i < NBINS; i += 256) g_binstart[cb][i] = off[i];
    if (tid == 0) g_binstart[cb][NBINS] = NPTS;
    __syncthreads();
    for (int i = tid; i < NPTS; i += 256) {
        float4 p = g_pts[cb][i];
        int pos = atomicAdd(&off[bin_of(p.x, p.y)], 1);
        g_sorted[cb][pos] = p;
    }
}

// ---------------------------------------------------------------------------
// 3-NN via ring search over bins. grid=(32,4), 256 thr, 4 grid pts/thread.
// ---------------------------------------------------------------------------
__global__ void __launch_bounds__(256) k_interp() {
    __shared__ float4 spt[NPTS];
    __shared__ int    sbin[NBINS + 1];
    int cb  = blockIdx.y;
    int tid = threadIdx.x;
    for (int i = tid; i < NPTS; i += 256) spt[i] = g_sorted[cb][i];
    for (int i = tid; i < NBINS + 1; i += 256) sbin[i] = g_binstart[cb][i];
    __syncthreads();

#pragma unroll
    for (int j = 0; j < 4; ++j) {
        int m = blockIdx.x * 1024 + j * 256 + tid;
        float gth = (float)(m >> 8) * (PI_F / NLAT);
        float gph = (float)((m & (NLON - 1)) - NLAT) * (PI_F / NLAT);
        int bt = min(max((int)(gth * INVH), 0), NBT - 1);
        int bp = min(max((int)((gph + PI_F) * INVH), 0), NBP - 1);

        float d0 = 3.4e38f, d1 = 3.4e38f, d2 = 3.4e38f;
        float r0 = 0.0f, r1 = 0.0f, r2 = 0.0f;

        for (int R = 0; R <= 64; ++R) {
            if (R > 0) {
                float lb = (float)(R - 1) * H_BIN;
                if (d2 <= lb * lb) break;
            }
            int t0 = max(bt - R, 0), t1 = min(bt + R, NBT - 1);
            int p0 = max(bp - R, 0), p1 = min(bp + R, NBP - 1);
            for (int y = t0; y <= t1; ++y) {
                bool full = (R == 0) || (y == bt - R) || (y == bt + R);
                int xs = full ? p0 : (bp - R);
                int xe = full ? p1 : (bp + R);
                int xstep = full ? 1 : (2 * R);
                for (int x = xs; x <= xe; x += xstep) {
                    if (x < 0 || x > NBP - 1) continue;
                    int bi = y * NBP + x;
                    int s0 = sbin[bi], s1 = sbin[bi + 1];
                    for (int i = s0; i < s1; ++i) {
                        float4 p = spt[i];
                        float dx = gth - p.x, dy = gph - p.y;
                        float d = fmaf(dx, dx, dy * dy);
                        bool c0 = d < d0, c1 = d < d1, c2 = d < d2;
                        d2 = c1 ? d1 : (c2 ? d : d2);  r2 = c1 ? r1 : (c2 ? p.z : r2);
                        d1 = c0 ? d0 : (c1 ? d : d1);  r1 = c0 ? r0 : (c1 ? p.z : r1);
                        d0 = c0 ? d  : d0;             r0 = c0 ? p.z : r0;
                    }
                }
            }
        }
        float s = d0 + d1 + d2;
        g_grid[cb][m] = (d0 * r0 + d1 * r1 + d2 * r2) / s;
    }
}

// ---------------------------------------------------------------------------
// Re(rfft)*2pi/NLON via Chebyshev cos recurrence. 4 rows/block, 256 threads.
// ---------------------------------------------------------------------------
__global__ void __launch_bounds__(256) k_rexf() {
    __shared__ float row[4][NLON];
    int tid = threadIdx.x;
    int grp = tid >> 6;        // row within block
    int m   = tid & 63;
    for (int i = tid; i < 4 * NLON; i += 256) {
        int rr = blockIdx.x * 4 + (i >> 8);
        row[i >> 8][i & (NLON - 1)] = ((const float*)g_grid)[rr * NLON + (i & (NLON - 1))];
    }
    __syncthreads();
    if (m < MMAX) {
        int rid = blockIdx.x * 4 + grp;       // combo*NLAT + k
        float alpha = (2.0f * PI_F / NLON) * (float)m;
        float twoc  = 2.0f * cosf(alpha);
        float cm1 = 1.0f;
        float c   = cosf(alpha);
        const float* rw = row[grp];
        float acc = rw[0];
        for (int n = 1; n < NLON; ++n) {
            acc = fmaf(rw[n], c, acc);
            float cn = fmaf(twoc, c, -cm1);
            cm1 = c; c = cn;
        }
        int combo = rid >> 7;  // /NLAT
        int k     = rid & (NLAT - 1);
        g_rexf[combo][m][k] = acc * (2.0f * PI_F / NLON);
    }
}

// ---------------------------------------------------------------------------
// coefficients + weighted squared diff, one warp per (b,l,m). grid=625x256.
// ---------------------------------------------------------------------------
__global__ void __launch_bounds__(256) k_coef() {
    int gwid = (blockIdx.x * 256 + threadIdx.x) >> 5;
    int lane = threadIdx.x & 31;
    if (gwid >= NB * LMAX * MMAX) return;
    int b = gwid / (LMAX * MMAX);
    int r = gwid % (LMAX * MMAX);
    int l = r / MMAX;
    int m = r % MMAX;
    const float* pw = g_pctw[m][l];
    const float* xp = g_rexf[b][m];        // combo = 0*2+b (pred)
    const float* xt = g_rexf[2 + b][m];    // combo = 1*2+b (target)
    float pc = 0.0f, tc = 0.0f;
#pragma unroll
    for (int k = lane; k < NLAT; k += 32) {
        float w = pw[k];
        pc = fmaf(xp[k], w, pc);
        tc = fmaf(xt[k], w, tc);
    }
#pragma unroll
    for (int o = 16; o > 0; o >>= 1) {
        pc += __shfl_down_sync(0xffffffffu, pc, o);
        tc += __shfl_down_sync(0xffffffffu, tc, o);
    }
    if (lane == 0) {
        float d = pc - tc;
        float q = (float)(LMAX - 1 - l);
        g_part[gwid] = d * d * expf(-q * q / (2.0f * LMAX * LMAX));
    }
}

// ---------------------------------------------------------------------------
// deterministic final reduction of 5000 partials. single block.
// ---------------------------------------------------------------------------
__global__ void __launch_bounds__(1024) k_final(float* __restrict__ out) {
    __shared__ float red[32];
    int tid = threadIdx.x;
    float acc = 0.0f;
    for (int i = tid; i < NB * LMAX * MMAX; i += 1024) acc += g_part[i];
#pragma unroll
    for (int o = 16; o > 0; o >>= 1) acc += __shfl_down_sync(0xffffffffu, acc, o);
    if ((tid & 31) == 0) red[tid >> 5] = acc;
    __syncthreads();
    if (tid < 32) {
        float v = red[tid];
#pragma unroll
        for (int o = 16; o > 0; o >>= 1) v += __shfl_down_sync(0xffffffffu, v, o);
        if (tid == 0) out[0] = v / (float)NB;
    }
}

extern "C" void kernel_launch(void* const* d_in, const int* in_sizes, int n_in,
                              void* d_out, int out_size) {
    const float* pred = (const float*)d_in[0];
    const float* tgt  = (const float*)d_in[1];
    k_pctw<<<MMAX, NLAT>>>();
    k_sph<<<(4 * NPTS + 255) / 256, 256>>>(pred, tgt);
    k_bin<<<4, 256>>>();
    dim3 gi(MG / 1024, 4);
    k_interp<<<gi, 256>>>();
    k_rexf<<<4 * NLAT / 4, 256>>>();
    k_coef<<<(NB * LMAX * MMAX + 7) / 8, 256>>>();
    k_final<<<1, 1024>>>((float*)d_out);
}

// round 5
// speedup vs baseline: 7.6799x; 1.0061x over previous
#include <cuda_runtime.h>
#include <math.h>

#define NLAT 128
#define NLON 256
#define LMAX 50
#define MMAX 50
#define NPTS 2048
#define NB   2
#define MG   (NLAT*NLON)
#define NBT  32
#define NBP  64
#define NBINS (NBT*NBP)
#define PI_F 3.14159265358979323846f
#define H_BIN (PI_F/32.0f)
#define INVH  (32.0f/PI_F)
#define CAP   1536

// scratch (device globals; no allocation allowed)
__device__ float4 g_sorted[4][NPTS];          // bin-sorted points (theta,phi,r,-)
__device__ int    g_binstart[4][NBINS + 1];
__device__ float  g_grid[4][MG];              // interpolated grids
__device__ float  g_pctw[MMAX][LMAX][NLAT];   // legendre * quadrature weight
__device__ float  g_rexf[4][MMAX][NLAT];      // Re(rfft)*2pi/NLON, m-major
__device__ float  g_part[NB*LMAX*MMAX];

__device__ __forceinline__ int bin_of(float th, float ph) {
    int bt = (int)(th * INVH);
    int bp = (int)((ph + PI_F) * INVH);
    bt = min(max(bt, 0), NBT - 1);
    bp = min(max(bp, 0), NBP - 1);
    return bt * NBP + bp;
}

// ---------------------------------------------------------------------------
// Legendre * Clenshaw-Curtis weight table
// ---------------------------------------------------------------------------
__global__ void k_pctw() {
    int m = blockIdx.x;
    int k = threadIdx.x;
    float theta = PI_F * (float)k / (float)(NLAT - 1);
    float cost  = cosf(theta);
    float sint  = sqrtf(fmaxf(1.0f - cost * cost, 0.0f));
    float v = 0.0f;
    for (int j = 1; j <= (NLAT - 1) / 2; ++j)
        v += 2.0f * cosf(2.0f * (float)j * theta) / (4.0f * (float)j * (float)j - 1.0f);
    float w = (2.0f / (float)(NLAT - 1)) * (1.0f - v);
    if (k == 0 || k == NLAT - 1) w *= 0.5f;
    float pmm = sqrtf(1.0f / (4.0f * PI_F));
    for (int mm = 1; mm <= m; ++mm)
        pmm = -pmm * sqrtf((2.0f * mm + 1.0f) / (2.0f * mm)) * sint;
    for (int l = 0; l < m; ++l) g_pctw[m][l][k] = 0.0f;
    g_pctw[m][m][k] = pmm * w;
    if (m + 1 < LMAX) {
        float plm2 = pmm;
        float plm1 = sqrtf(2.0f * m + 3.0f) * cost * pmm;
        g_pctw[m][m + 1][k] = plm1 * w;
        for (int l = m + 2; l < LMAX; ++l) {
            float fl = (float)l, fm = (float)m;
            float a = sqrtf((4.0f * fl * fl - 1.0f) / (fl * fl - fm * fm));
            float b = sqrtf(((2.0f * fl + 1.0f) * (fl - 1.0f + fm) * (fl - 1.0f - fm)) /
                            ((2.0f * fl - 3.0f) * (fl * fl - fm * fm)));
            float pl = a * cost * plm1 - b * plm2;
            g_pctw[m][l][k] = pl * w;
            plm2 = plm1; plm1 = pl;
        }
    }
}

// ---------------------------------------------------------------------------
// fused: cartesian->spherical + counting-sort into bins. 4 blocks x 512.
// ---------------------------------------------------------------------------
__global__ void __launch_bounds__(512) k_prep(const float* __restrict__ pred,
                                             const float* __restrict__ tgt) {
    __shared__ float4 pts[NPTS];
    __shared__ int cnt[NBINS];
    __shared__ int off[NBINS];
    __shared__ int wsum[16];
    int cb  = blockIdx.x;
    int tid = threadIdx.x;
    int t = cb >> 1, b = cb & 1;
    const float* src = (t ? tgt : pred) + (size_t)b * NPTS * 3;
    for (int i = tid; i < NBINS; i += 512) cnt[i] = 0;
    __syncthreads();
    for (int i = tid; i < NPTS; i += 512) {
        float x = src[3 * i], y = src[3 * i + 1], z = src[3 * i + 2];
        float r   = sqrtf(x * x + y * y + z * z);
        float pn1 = sqrtf(y * y + z * z);
        float th  = acosf(fminf(fmaxf(x / r,   -1.0f), 1.0f));
        float a   = acosf(fminf(fmaxf(y / pn1, -1.0f), 1.0f));
        float ph  = ((z < 0.0f) ? (2.0f * PI_F - a) : a) - PI_F;
        float4 o; o.x = th; o.y = ph; o.z = r; o.w = 0.0f;
        pts[i] = o;
        atomicAdd(&cnt[bin_of(th, ph)], 1);
    }
    __syncthreads();
    // exclusive scan over 2048 bins (4/thread)
    int base = tid * 4;
    int local[4]; int s = 0;
#pragma unroll
    for (int j = 0; j < 4; ++j) { local[j] = s; s += cnt[base + j]; }
    int lane = tid & 31, wrp = tid >> 5;
    int v = s;
#pragma unroll
    for (int o = 1; o < 32; o <<= 1) {
        int u = __shfl_up_sync(0xffffffffu, v, o);
        if (lane >= o) v += u;
    }
    if (lane == 31) wsum[wrp] = v;
    __syncthreads();
    if (tid == 0) { int a = 0; for (int j = 0; j < 16; ++j) { int x = wsum[j]; wsum[j] = a; a += x; } }
    __syncthreads();
    int excl = v - s + wsum[wrp];
#pragma unroll
    for (int j = 0; j < 4; ++j) off[base + j] = excl + local[j];
    __syncthreads();
    for (int i = tid; i < NBINS; i += 512) g_binstart[cb][i] = off[i];
    if (tid == 0) g_binstart[cb][NBINS] = NPTS;
    __syncthreads();
    for (int i = tid; i < NPTS; i += 512) {
        float4 p = pts[i];
        int pos = atomicAdd(&off[bin_of(p.x, p.y)], 1);
        g_sorted[cb][pos] = p;
    }
}

// ---------------------------------------------------------------------------
// 3-NN interp: block = 16x16 grid tile (=4x4 bins) + 3-bin halo candidates
// in SMEM; uniform branch-free scan; rare ring-search fallback (poles).
// grid = (16, 8, 4), block = 256.
// ---------------------------------------------------------------------------
__global__ void __launch_bounds__(256) k_interp() {
    __shared__ float4 cand[CAP];
    __shared__ int rowoff[12], rowsrc[12];
    int cb  = blockIdx.z;
    int tid = threadIdx.x;
    int bt0 = blockIdx.y * 4, bp0 = blockIdx.x * 4;
    int ht0 = max(bt0 - 3, 0), ht1 = min(bt0 + 6, NBT - 1);
    int hp0 = max(bp0 - 3, 0), hp1 = min(bp0 + 6, NBP - 1);
    int nrows = ht1 - ht0 + 1;
    if (tid == 0) {
        int off = 0;
        for (int r = 0; r < nrows; ++r) {
            int s = g_binstart[cb][(ht0 + r) * NBP + hp0];
            int e = g_binstart[cb][(ht0 + r) * NBP + hp1 + 1];
            rowsrc[r] = s;
            rowoff[r] = off;
            off += e - s;
        }
        rowoff[nrows] = off;
    }
    __syncthreads();
    int ncand = rowoff[nrows];
    bool ovf = ncand > CAP;
    if (!ovf) {
        for (int r = 0; r < nrows; ++r) {
            int o0 = rowoff[r], len = rowoff[r + 1] - o0, s0 = rowsrc[r];
            for (int i = tid; i < len; i += 256) cand[o0 + i] = g_sorted[cb][s0 + i];
        }
    }
    __syncthreads();

    int ty = tid >> 4, tx = tid & 15;
    int irow = blockIdx.y * 16 + ty;
    int icol = blockIdx.x * 16 + tx;
    float gth = (float)irow * (PI_F / NLAT);
    float gph = (float)(icol - NLAT) * (PI_F / NLAT);

    float d0 = 3.4e38f, d1 = 3.4e38f, d2 = 3.4e38f;
    float r0 = 0.0f, r1 = 0.0f, r2 = 0.0f;

    if (!ovf) {
#pragma unroll 4
        for (int i = 0; i < ncand; ++i) {
            float4 p = cand[i];
            float dx = gth - p.x, dy = gph - p.y;
            float d = fmaf(dx, dx, dy * dy);
            bool c0 = d < d0, c1 = d < d1, c2 = d < d2;
            d2 = c1 ? d1 : (c2 ? d : d2);  r2 = c1 ? r1 : (c2 ? p.z : r2);
            d1 = c0 ? d0 : (c1 ? d : d1);  r1 = c0 ? r0 : (c1 ? p.z : r1);
            d0 = c0 ? d  : d0;             r0 = c0 ? p.z : r0;
        }
    }

    // fallback ring search (rare: poles, or smem overflow)
    if (ovf || d2 > 9.0f * H_BIN * H_BIN) {
        int bt = min(irow >> 2, NBT - 1);
        int bp = min(icol >> 2, NBP - 1);
        int st0 = ovf ? 1000 : ht0, st1 = ovf ? -1 : ht1;
        int sp0 = ovf ? 1000 : hp0, sp1 = ovf ? -1 : hp1;
        int Rstart = ovf ? 0 : 4;
        for (int R = Rstart; R <= 64; ++R) {
            if (R > 0) {
                float lb = (float)(R - 1) * H_BIN;
                if (d2 <= lb * lb) break;
            }
            int t0 = max(bt - R, 0), t1 = min(bt + R, NBT - 1);
            int p0 = max(bp - R, 0), p1 = min(bp + R, NBP - 1);
            for (int y = t0; y <= t1; ++y) {
                bool full = (R == 0) || (y == bt - R) || (y == bt + R);
                int xs = full ? p0 : (bp - R);
                int xe = full ? p1 : (bp + R);
                int xstep = full ? 1 : (2 * R);
                for (int x = xs; x <= xe; x += xstep) {
                    if (x < 0 || x > NBP - 1) continue;
                    if (y >= st0 && y <= st1 && x >= sp0 && x <= sp1) continue;
                    int bi = y * NBP + x;
                    int s0 = g_binstart[cb][bi], s1 = g_binstart[cb][bi + 1];
                    for (int i = s0; i < s1; ++i) {
                        float4 p = g_sorted[cb][i];
                        float dx = gth - p.x, dy = gph - p.y;
                        float d = fmaf(dx, dx, dy * dy);
                        bool c0 = d < d0, c1 = d < d1, c2 = d < d2;
                        d2 = c1 ? d1 : (c2 ? d : d2);  r2 = c1 ? r1 : (c2 ? p.z : r2);
                        d1 = c0 ? d0 : (c1 ? d : d1);  r1 = c0 ? r0 : (c1 ? p.z : r1);
                        d0 = c0 ? d  : d0;             r0 = c0 ? p.z : r0;
                    }
                }
            }
        }
    }

    float s = d0 + d1 + d2;
    g_grid[cb][irow * NLON + icol] = (d0 * r0 + d1 * r1 + d2 * r2) / s;
}

// ---------------------------------------------------------------------------
// Re(rfft)*2pi/NLON. fold n<->n+128, 4 interleaved Chebyshev chains.
// 4 rows/block, 256 threads (64 m-slots x 4 rows).
// ---------------------------------------------------------------------------
__global__ void __launch_bounds__(256) k_rexf() {
    __shared__ float row[4][NLON];
    int tid = threadIdx.x;
    int grp = tid >> 6;
    int m   = tid & 63;
    for (int i = tid; i < 4 * NLON; i += 256) {
        int rr = blockIdx.x * 4 + (i >> 8);
        row[i >> 8][i & (NLON - 1)] = ((const float*)g_grid)[rr * NLON + (i & (NLON - 1))];
    }
    __syncthreads();
    if (m < MMAX) {
        const float* rw = row[grp];
        float beta = (PI_F / 128.0f) * (float)m;
        float sgn  = (m & 1) ? -1.0f : 1.0f;
        float c4   = 2.0f * cosf(4.0f * beta);
        float cur0 = 1.0f,             nxt0 = cosf(4.0f * beta);
        float cur1 = cosf(beta),        nxt1 = cosf(5.0f * beta);
        float cur2 = cosf(2.0f * beta), nxt2 = cosf(6.0f * beta);
        float cur3 = cosf(3.0f * beta), nxt3 = cosf(7.0f * beta);
        float a0 = 0.0f, a1 = 0.0f, a2 = 0.0f, a3 = 0.0f;
#pragma unroll 4
        for (int k = 0; k < 32; ++k) {
            int n = 4 * k;
            float v0 = fmaf(sgn, rw[n + 128],     rw[n]);
            float v1 = fmaf(sgn, rw[n + 129],     rw[n + 1]);
            float v2 = fmaf(sgn, rw[n + 130],     rw[n + 2]);
            float v3 = fmaf(sgn, rw[n + 131],     rw[n + 3]);
            a0 = fmaf(v0, cur0, a0);
            a1 = fmaf(v1, cur1, a1);
            a2 = fmaf(v2, cur2, a2);
            a3 = fmaf(v3, cur3, a3);
            float t0 = fmaf(c4, nxt0, -cur0); cur0 = nxt0; nxt0 = t0;
            float t1 = fmaf(c4, nxt1, -cur1); cur1 = nxt1; nxt1 = t1;
            float t2 = fmaf(c4, nxt2, -cur2); cur2 = nxt2; nxt2 = t2;
            float t3 = fmaf(c4, nxt3, -cur3); cur3 = nxt3; nxt3 = t3;
        }
        float acc = (a0 + a1) + (a2 + a3);
        int rid = blockIdx.x * 4 + grp;
        int combo = rid >> 7;
        int k = rid & (NLAT - 1);
        g_rexf[combo][m][k] = acc * (2.0f * PI_F / NLON);
    }
}

// ---------------------------------------------------------------------------
// coefficients + weighted squared diff, one warp per (b,l,m)
// ---------------------------------------------------------------------------
__global__ void __launch_bounds__(256) k_coef() {
    int gwid = (blockIdx.x * 256 + threadIdx.x) >> 5;
    int lane = threadIdx.x & 31;
    if (gwid >= NB * LMAX * MMAX) return;
    int b = gwid / (LMAX * MMAX);
    int r = gwid % (LMAX * MMAX);
    int l = r / MMAX;
    int m = r % MMAX;
    const float* pw = g_pctw[m][l];
    const float* xp = g_rexf[b][m];
    const float* xt = g_rexf[2 + b][m];
    float pc = 0.0f, tc = 0.0f;
#pragma unroll
    for (int k = lane; k < NLAT; k += 32) {
        float w = pw[k];
        pc = fmaf(xp[k], w, pc);
        tc = fmaf(xt[k], w, tc);
    }
#pragma unroll
    for (int o = 16; o > 0; o >>= 1) {
        pc += __shfl_down_sync(0xffffffffu, pc, o);
        tc += __shfl_down_sync(0xffffffffu, tc, o);
    }
    if (lane == 0) {
        float d = pc - tc;
        float q = (float)(LMAX - 1 - l);
        g_part[gwid] = d * d * expf(-q * q / (2.0f * LMAX * LMAX));
    }
}

__global__ void __launch_bounds__(1024) k_final(float* __restrict__ out) {
    __shared__ float red[32];
    int tid = threadIdx.x;
    float acc = 0.0f;
    for (int i = tid; i < NB * LMAX * MMAX; i += 1024) acc += g_part[i];
#pragma unroll
    for (int o = 16; o > 0; o >>= 1) acc += __shfl_down_sync(0xffffffffu, acc, o);
    if ((tid & 31) == 0) red[tid >> 5] = acc;
    __syncthreads();
    if (tid < 32) {
        float v = red[tid];
#pragma unroll
        for (int o = 16; o > 0; o >>= 1) v += __shfl_down_sync(0xffffffffu, v, o);
        if (tid == 0) out[0] = v / (float)NB;
    }
}

extern "C" void kernel_launch(void* const* d_in, const int* in_sizes, int n_in,
                              void* d_out, int out_size) {
    const float* pred = (const float*)d_in[0];
    const float* tgt  = (const float*)d_in[1];
    k_prep<<<4, 512>>>(pred, tgt);
    k_pctw<<<MMAX, NLAT>>>();
    dim3 gi(16, 8, 4);
    k_interp<<<gi, 256>>>();
    k_rexf<<<4 * NLAT / 4, 256>>>();
    k_coef<<<(NB * LMAX * MMAX + 7) / 8, 256>>>();
    k_final<<<1, 1024>>>((float*)d_out);
}

// round 6
// speedup vs baseline: 10.3752x; 1.3510x over previous
#include <cuda_runtime.h>
#include <math.h>

#define NLAT 128
#define NLON 256
#define LMAX 50
#define MMAX 50
#define NPTS 2048
#define NB   2
#define MG   (NLAT*NLON)
#define NBT  32
#define NBP  64
#define NBINS (NBT*NBP)
#define PI_F 3.14159265358979323846f
#define H_BIN (PI_F/32.0f)
#define INVH  (32.0f/PI_F)
#define CAP   1536
#define NBLK  512

// ---- device scratch (globals; zero-init at load) ----
__device__ float4 g_pts   [4][NPTS];
__device__ float4 g_sorted[4][NPTS];
__device__ int    g_binstart[4][NBINS + 1];
__device__ float  g_grid[4][MG];
__device__ float  g_pctw[MMAX][LMAX][NLAT];
__device__ float  g_rexf[4][MMAX][NLAT];
__device__ float  g_part[NB * LMAX * MMAX];
__device__ int    g_barc[4];
__device__ int    g_barl[4];

union Smem {
    struct { int cnt[NBINS]; int off[NBINS]; int wsum[8]; } prep;
    struct { float4 cand[CAP]; int rowoff[12]; int rowsrc[12]; } it;
    struct { float row[NLON]; float ctab[NLON]; } rx;
    float red[64];
};

__device__ __forceinline__ void gbar(int id) {
    __syncthreads();
    if (threadIdx.x == 0) {
        __threadfence();
        atomicAdd(&g_barc[id], 1);
        while (*(volatile int*)&g_barc[id] < NBLK) { }
        __threadfence();
        int l = atomicAdd(&g_barl[id], 1);
        if (l == NBLK - 1) {               // last to leave resets for next replay
            *(volatile int*)&g_barc[id] = 0;
            *(volatile int*)&g_barl[id] = 0;
            __threadfence();
        }
    }
    __syncthreads();
}

__device__ __forceinline__ int bin_of(float th, float ph) {
    int bt = (int)(th * INVH);
    int bp = (int)((ph + PI_F) * INVH);
    bt = min(max(bt, 0), NBT - 1);
    bp = min(max(bp, 0), NBP - 1);
    return bt * NBP + bp;
}

__global__ void __launch_bounds__(256, 4)
k_mega(const float* __restrict__ pred, const float* __restrict__ tgt,
       float* __restrict__ out) {
    __shared__ Smem sm;
    int bid = blockIdx.x;
    int tid = threadIdx.x;
    int lane = tid & 31;
    int wid  = tid >> 5;

    // ======================= Phase A: prep (blocks 0-3) + pctw (4-28) =======
    if (bid < 4) {
        int cb = bid;
        int t = cb >> 1, b = cb & 1;
        const float* src = (t ? tgt : pred) + (size_t)b * NPTS * 3;
        for (int i = tid; i < NBINS; i += 256) sm.prep.cnt[i] = 0;
        __syncthreads();
        for (int i = tid; i < NPTS; i += 256) {
            float x = src[3 * i], y = src[3 * i + 1], z = src[3 * i + 2];
            float r   = sqrtf(x * x + y * y + z * z);
            float pn1 = sqrtf(y * y + z * z);
            float th  = acosf(fminf(fmaxf(x / r,   -1.0f), 1.0f));
            float a   = acosf(fminf(fmaxf(y / pn1, -1.0f), 1.0f));
            float ph  = ((z < 0.0f) ? (2.0f * PI_F - a) : a) - PI_F;
            float4 o; o.x = th; o.y = ph; o.z = r; o.w = 0.0f;
            g_pts[cb][i] = o;
            atomicAdd(&sm.prep.cnt[bin_of(th, ph)], 1);
        }
        __syncthreads();
        // exclusive scan over 2048 bins, 8/thread
        int base = tid * 8;
        int local[8]; int s = 0;
#pragma unroll
        for (int j = 0; j < 8; ++j) { local[j] = s; s += sm.prep.cnt[base + j]; }
        int v = s;
#pragma unroll
        for (int o = 1; o < 32; o <<= 1) {
            int u = __shfl_up_sync(0xffffffffu, v, o);
            if (lane >= o) v += u;
        }
        if (lane == 31) sm.prep.wsum[wid] = v;
        __syncthreads();
        if (tid == 0) {
            int a = 0;
            for (int j = 0; j < 8; ++j) { int x = sm.prep.wsum[j]; sm.prep.wsum[j] = a; a += x; }
        }
        __syncthreads();
        int excl = v - s + sm.prep.wsum[wid];
#pragma unroll
        for (int j = 0; j < 8; ++j) sm.prep.off[base + j] = excl + local[j];
        __syncthreads();
        for (int i = tid; i < NBINS; i += 256) g_binstart[cb][i] = sm.prep.off[i];
        if (tid == 0) g_binstart[cb][NBINS] = NPTS;
        __syncthreads();
        for (int i = tid; i < NPTS; i += 256) {
            float4 p = g_pts[cb][i];
            int pos = atomicAdd(&sm.prep.off[bin_of(p.x, p.y)], 1);
            g_sorted[cb][pos] = p;
        }
    } else if (bid < 29) {
        // pctw: 2 m-values per block (128 threads each)
        int m = (bid - 4) * 2 + (tid >> 7);
        int k = tid & 127;
        if (m < MMAX) {
            float theta = PI_F * (float)k / (float)(NLAT - 1);
            float cost  = cosf(theta);
            float sint  = sqrtf(fmaxf(1.0f - cost * cost, 0.0f));
            float v = 0.0f;
            for (int j = 1; j <= (NLAT - 1) / 2; ++j)
                v += 2.0f * cosf(2.0f * (float)j * theta) / (4.0f * (float)j * (float)j - 1.0f);
            float w = (2.0f / (float)(NLAT - 1)) * (1.0f - v);
            if (k == 0 || k == NLAT - 1) w *= 0.5f;
            float pmm = sqrtf(1.0f / (4.0f * PI_F));
            for (int mm = 1; mm <= m; ++mm)
                pmm = -pmm * sqrtf((2.0f * mm + 1.0f) / (2.0f * mm)) * sint;
            for (int l = 0; l < m; ++l) g_pctw[m][l][k] = 0.0f;
            g_pctw[m][m][k] = pmm * w;
            if (m + 1 < LMAX) {
                float plm2 = pmm;
                float plm1 = sqrtf(2.0f * m + 3.0f) * cost * pmm;
                g_pctw[m][m + 1][k] = plm1 * w;
                for (int l = m + 2; l < LMAX; ++l) {
                    float fl = (float)l, fm = (float)m;
                    float a = sqrtf((4.0f * fl * fl - 1.0f) / (fl * fl - fm * fm));
                    float bq = sqrtf(((2.0f * fl + 1.0f) * (fl - 1.0f + fm) * (fl - 1.0f - fm)) /
                                     ((2.0f * fl - 3.0f) * (fl * fl - fm * fm)));
                    float pl = a * cost * plm1 - bq * plm2;
                    g_pctw[m][l][k] = pl * w;
                    plm2 = plm1; plm1 = pl;
                }
            }
        }
    }
    gbar(0);

    // ======================= Phase B: 3-NN interp (all 512 blocks) ==========
    {
        int cb  = bid >> 7;
        int rem = bid & 127;
        int ty8 = rem >> 4, tx16 = rem & 15;
        int bt0 = ty8 * 4, bp0 = tx16 * 4;
        int ht0 = max(bt0 - 3, 0), ht1 = min(bt0 + 6, NBT - 1);
        int hp0 = max(bp0 - 3, 0), hp1 = min(bp0 + 6, NBP - 1);
        int nrows = ht1 - ht0 + 1;
        if (tid == 0) {
            int off = 0;
            for (int r = 0; r < nrows; ++r) {
                int s = g_binstart[cb][(ht0 + r) * NBP + hp0];
                int e = g_binstart[cb][(ht0 + r) * NBP + hp1 + 1];
                sm.it.rowsrc[r] = s;
                sm.it.rowoff[r] = off;
                off += e - s;
            }
            sm.it.rowoff[nrows] = off;
        }
        __syncthreads();
        int ncand = sm.it.rowoff[nrows];
        bool ovf = ncand > CAP;
        if (!ovf) {
            for (int r = 0; r < nrows; ++r) {
                int o0 = sm.it.rowoff[r], len = sm.it.rowoff[r + 1] - o0, s0 = sm.it.rowsrc[r];
                for (int i = tid; i < len; i += 256) sm.it.cand[o0 + i] = g_sorted[cb][s0 + i];
            }
        }
        __syncthreads();

        int irow = ty8 * 16 + (tid >> 4);
        int icol = tx16 * 16 + (tid & 15);
        float gth = (float)irow * (PI_F / NLAT);
        float gph = (float)(icol - NLAT) * (PI_F / NLAT);

        float d0 = 3.4e38f, d1 = 3.4e38f, d2 = 3.4e38f;
        float r0 = 0.0f, r1 = 0.0f, r2 = 0.0f;

        if (!ovf) {
#pragma unroll 4
            for (int i = 0; i < ncand; ++i) {
                float4 p = sm.it.cand[i];
                float dx = gth - p.x, dy = gph - p.y;
                float d = fmaf(dx, dx, dy * dy);
                bool c0 = d < d0, c1 = d < d1, c2 = d < d2;
                d2 = c1 ? d1 : (c2 ? d : d2);  r2 = c1 ? r1 : (c2 ? p.z : r2);
                d1 = c0 ? d0 : (c1 ? d : d1);  r1 = c0 ? r0 : (c1 ? p.z : r1);
                d0 = c0 ? d  : d0;             r0 = c0 ? p.z : r0;
            }
        }

        if (ovf || d2 > 9.0f * H_BIN * H_BIN) {
            int bt = min(irow >> 2, NBT - 1);
            int bp = min(icol >> 2, NBP - 1);
            int st0 = ovf ? 1000 : ht0, st1 = ovf ? -1 : ht1;
            int sp0 = ovf ? 1000 : hp0, sp1 = ovf ? -1 : hp1;
            int Rstart = ovf ? 0 : 4;
            for (int R = Rstart; R <= 64; ++R) {
                if (R > 0) {
                    float lb = (float)(R - 1) * H_BIN;
                    if (d2 <= lb * lb) break;
                }
                int t0 = max(bt - R, 0), t1 = min(bt + R, NBT - 1);
                int p0 = max(bp - R, 0), p1 = min(bp + R, NBP - 1);
                for (int y = t0; y <= t1; ++y) {
                    bool full = (R == 0) || (y == bt - R) || (y == bt + R);
                    int xs = full ? p0 : (bp - R);
                    int xe = full ? p1 : (bp + R);
                    int xstep = full ? 1 : (2 * R);
                    for (int x = xs; x <= xe; x += xstep) {
                        if (x < 0 || x > NBP - 1) continue;
                        if (y >= st0 && y <= st1 && x >= sp0 && x <= sp1) continue;
                        int bi = y * NBP + x;
                        int s0 = g_binstart[cb][bi], s1 = g_binstart[cb][bi + 1];
                        for (int i = s0; i < s1; ++i) {
                            float4 p = g_sorted[cb][i];
                            float dx = gth - p.x, dy = gph - p.y;
                            float d = fmaf(dx, dx, dy * dy);
                            bool c0 = d < d0, c1 = d < d1, c2 = d < d2;
                            d2 = c1 ? d1 : (c2 ? d : d2);  r2 = c1 ? r1 : (c2 ? p.z : r2);
                            d1 = c0 ? d0 : (c1 ? d : d1);  r1 = c0 ? r0 : (c1 ? p.z : r1);
                            d0 = c0 ? d  : d0;             r0 = c0 ? p.z : r0;
                        }
                    }
                }
            }
        }
        float s = d0 + d1 + d2;
        g_grid[cb][irow * NLON + icol] = (d0 * r0 + d1 * r1 + d2 * r2) / s;
    }
    gbar(1);

    // ======================= Phase C: DFT real part (block = grid row) ======
    {
        int combo = bid >> 7;
        int k     = bid & 127;
        sm.rx.row[tid]  = g_grid[combo][k * NLON + tid];
        float ang = (2.0f * PI_F / NLON) * (float)tid;
        sm.rx.ctab[tid] = cosf(ang);
        // second half (tid covers 0..255 since blockDim=256)
        __syncthreads();
        for (int m = wid; m < MMAX; m += 8) {
            float acc = 0.0f;
#pragma unroll
            for (int j = 0; j < 8; ++j) {
                int n = lane + 32 * j;
                acc = fmaf(sm.rx.row[n], sm.rx.ctab[(m * n) & (NLON - 1)], acc);
            }
#pragma unroll
            for (int o = 16; o > 0; o >>= 1) acc += __shfl_down_sync(0xffffffffu, acc, o);
            if (lane == 0) g_rexf[combo][m][k] = acc * (2.0f * PI_F / NLON);
        }
    }
    gbar(2);

    // ======================= Phase D: coefficients + partial loss ===========
    {
        int gw0 = bid * 8 + wid;                 // 4096 warps
        for (int task = gw0; task < NB * LMAX * MMAX; task += 4096) {
            int b = task / (LMAX * MMAX);
            int r = task % (LMAX * MMAX);
            int l = r / MMAX;
            int m = r % MMAX;
            const float* pw = g_pctw[m][l];
            const float* xp = g_rexf[b][m];
            const float* xt = g_rexf[2 + b][m];
            float pc = 0.0f, tc = 0.0f;
#pragma unroll
            for (int k = lane; k < NLAT; k += 32) {
                float w = pw[k];
                pc = fmaf(xp[k], w, pc);
                tc = fmaf(xt[k], w, tc);
            }
#pragma unroll
            for (int o = 16; o > 0; o >>= 1) {
                pc += __shfl_down_sync(0xffffffffu, pc, o);
                tc += __shfl_down_sync(0xffffffffu, tc, o);
            }
            if (lane == 0) {
                float d = pc - tc;
                float q = (float)(LMAX - 1 - l);
                g_part[task] = d * d * expf(-q * q / (2.0f * LMAX * LMAX));
            }
        }
    }
    gbar(3);

    // ======================= Final reduce (block 0, deterministic) ==========
    if (bid == 0) {
        float acc = 0.0f;
        for (int i = tid; i < NB * LMAX * MMAX; i += 256) acc += g_part[i];
#pragma unroll
        for (int o = 16; o > 0; o >>= 1) acc += __shfl_down_sync(0xffffffffu, acc, o);
        if (lane == 0) sm.red[wid] = acc;
        __syncthreads();
        if (tid == 0) {
            float v = 0.0f;
            for (int j = 0; j < 8; ++j) v += sm.red[j];
            out[0] = v / (float)NB;
        }
    }
}

extern "C" void kernel_launch(void* const* d_in, const int* in_sizes, int n_in,
                              void* d_out, int out_size) {
    const float* pred = (const float*)d_in[0];
    const float* tgt  = (const float*)d_in[1];
    k_mega<<<NBLK, 256>>>(pred, tgt, (float*)d_out);
}

// round 7
// speedup vs baseline: 12.1412x; 1.1702x over previous
#include <cuda_runtime.h>
#include <math.h>

#define NLAT 128
#define NLON 256
#define LMAX 50
#define MMAX 50
#define NPTS 2048
#define NB   2
#define MG   (NLAT*NLON)
#define NBT  32
#define NBP  64
#define NBINS (NBT*NBP)
#define PI_F 3.14159265358979323846f
#define H_BIN (PI_F/32.0f)
#define INVH  (32.0f/PI_F)
#define CAP   1536
#define NBLK  512
#define KINF  0x7F7FFFFFu

// ---- device scratch (globals; zero-init at load) ----
__device__ float4 g_sorted[4][NPTS];
__device__ int    g_binstart[4][NBINS + 1];
__device__ float  g_grid[4][MG];
__device__ float  g_pctw[MMAX][LMAX][NLAT];
__device__ float  g_rexf[4][MMAX][NLAT];
__device__ float  g_part[NB * LMAX * MMAX];
__device__ int    g_barc[3 * 32];   // [id*32]=arrive, [id*32+1]=leave, padded lines
__device__ int    g_done;

union Smem {
    struct { float4 pts[NPTS]; int cnt[NBINS]; int wsum[8]; } prep;   // ~41KB
    struct { float4 cand[CAP]; int rowoff[12]; int rowsrc[12]; } it;  // ~24KB
    struct { float row[NLON]; float ctab[NLON]; } rx;
    float red[64];
};

__device__ __forceinline__ void gbar(int id) {
    __syncthreads();
    if (threadIdx.x == 0) {
        __threadfence();
        atomicAdd(&g_barc[id * 32], 1);
        while (*(volatile int*)&g_barc[id * 32] < NBLK) __nanosleep(128);
        __threadfence();
        int l = atomicAdd(&g_barc[id * 32 + 1], 1);
        if (l == NBLK - 1) {
            *(volatile int*)&g_barc[id * 32]     = 0;
            *(volatile int*)&g_barc[id * 32 + 1] = 0;
            __threadfence();
        }
    }
    __syncthreads();
}

__device__ __forceinline__ int bin_of(float th, float ph) {
    int bt = (int)(th * INVH);
    int bp = (int)((ph + PI_F) * INVH);
    bt = min(max(bt, 0), NBT - 1);
    bp = min(max(bp, 0), NBP - 1);
    return bt * NBP + bp;
}

__device__ __forceinline__ void ins3(unsigned& k0, unsigned& k1, unsigned& k2, unsigned key) {
    unsigned t  = max(k0, key); k0 = min(k0, key);
    unsigned t2 = max(k1, t);   k1 = min(k1, t);
    k2 = min(k2, t2);
}

__global__ void __launch_bounds__(256, 4)
k_mega(const float* __restrict__ pred, const float* __restrict__ tgt,
       float* __restrict__ out) {
    __shared__ Smem sm;
    __shared__ int s_last;
    int bid  = blockIdx.x;
    int tid  = threadIdx.x;
    int lane = tid & 31;
    int wid  = tid >> 5;

    // ================= Phase A: prep (blocks 0-3) + pctw (4-28) =============
    if (bid < 4) {
        int cb = bid;
        int t = cb >> 1, b = cb & 1;
        const float* src = (t ? tgt : pred) + (size_t)b * NPTS * 3;
        for (int i = tid; i < NBINS; i += 256) sm.prep.cnt[i] = 0;
        __syncthreads();
        for (int i = tid; i < NPTS; i += 256) {
            float x = src[3 * i], y = src[3 * i + 1], z = src[3 * i + 2];
            float r   = sqrtf(x * x + y * y + z * z);
            float pn1 = sqrtf(y * y + z * z);
            float th  = acosf(fminf(fmaxf(x / r,   -1.0f), 1.0f));
            float a   = acosf(fminf(fmaxf(y / pn1, -1.0f), 1.0f));
            float ph  = ((z < 0.0f) ? (2.0f * PI_F - a) : a) - PI_F;
            float4 o; o.x = th; o.y = ph; o.z = r; o.w = 0.0f;
            sm.prep.pts[i] = o;
            atomicAdd(&sm.prep.cnt[bin_of(th, ph)], 1);
        }
        __syncthreads();
        int base = tid * 8;
        int local[8]; int s = 0;
#pragma unroll
        for (int j = 0; j < 8; ++j) { local[j] = s; s += sm.prep.cnt[base + j]; }
        int v = s;
#pragma unroll
        for (int o = 1; o < 32; o <<= 1) {
            int u = __shfl_up_sync(0xffffffffu, v, o);
            if (lane >= o) v += u;
        }
        if (lane == 31) sm.prep.wsum[wid] = v;
        __syncthreads();
        if (tid == 0) {
            int a = 0;
            for (int j = 0; j < 8; ++j) { int x = sm.prep.wsum[j]; sm.prep.wsum[j] = a; a += x; }
        }
        __syncthreads();
        int excl = v - s + sm.prep.wsum[wid];
#pragma unroll
        for (int j = 0; j < 8; ++j) {
            int off = excl + local[j];
            sm.prep.cnt[base + j] = off;
            g_binstart[cb][base + j] = off;
        }
        if (tid == 0) g_binstart[cb][NBINS] = NPTS;
        __syncthreads();
        for (int i = tid; i < NPTS; i += 256) {
            float4 p = sm.prep.pts[i];
            int pos = atomicAdd(&sm.prep.cnt[bin_of(p.x, p.y)], 1);
            g_sorted[cb][pos] = p;
        }
    } else if (bid < 29) {
        int m = (bid - 4) * 2 + (tid >> 7);
        int k = tid & 127;
        if (m < MMAX) {
            float theta = PI_F * (float)k / (float)(NLAT - 1);
            float cost  = cosf(theta);
            float sint  = sqrtf(fmaxf(1.0f - cost * cost, 0.0f));
            float v = 0.0f;
            for (int j = 1; j <= (NLAT - 1) / 2; ++j)
                v += 2.0f * cosf(2.0f * (float)j * theta) / (4.0f * (float)j * (float)j - 1.0f);
            float w = (2.0f / (float)(NLAT - 1)) * (1.0f - v);
            if (k == 0 || k == NLAT - 1) w *= 0.5f;
            float pmm = sqrtf(1.0f / (4.0f * PI_F));
            for (int mm = 1; mm <= m; ++mm)
                pmm = -pmm * sqrtf((2.0f * mm + 1.0f) / (2.0f * mm)) * sint;
            for (int l = 0; l < m; ++l) g_pctw[m][l][k] = 0.0f;
            g_pctw[m][m][k] = pmm * w;
            if (m + 1 < LMAX) {
                float plm2 = pmm;
                float plm1 = sqrtf(2.0f * m + 3.0f) * cost * pmm;
                g_pctw[m][m + 1][k] = plm1 * w;
                for (int l = m + 2; l < LMAX; ++l) {
                    float fl = (float)l, fm = (float)m;
                    float a = sqrtf((4.0f * fl * fl - 1.0f) / (fl * fl - fm * fm));
                    float bq = sqrtf(((2.0f * fl + 1.0f) * (fl - 1.0f + fm) * (fl - 1.0f - fm)) /
                                     ((2.0f * fl - 3.0f) * (fl * fl - fm * fm)));
                    float pl = a * cost * plm1 - bq * plm2;
                    g_pctw[m][l][k] = pl * w;
                    plm2 = plm1; plm1 = pl;
                }
            }
        }
    }
    gbar(0);

    // ================= Phase B: 3-NN interp (512 tiles) =====================
    {
        int cb  = bid >> 7;
        int rem = bid & 127;
        int ty8 = rem >> 4, tx16 = rem & 15;
        int bt0 = ty8 * 4, bp0 = tx16 * 4;
        bool pole = (ty8 == 0) || (ty8 == 7);

        int irow = ty8 * 16 + (tid >> 4);
        int icol = tx16 * 16 + (tid & 15);
        float gth = (float)irow * (PI_F / NLAT);
        float gph = (float)(icol - NLAT) * (PI_F / NLAT);

        int ncand;
        float margin;
        int sk_t0, sk_t1, sk_p0, sk_p1;    // scanned (skip) rect in bin coords

        if (pole) {
            // whole polar cap: bin rows 0..6 (north) or 25..31 (south), all phi
            int r0 = (ty8 == 0) ? 0 : 25;
            int r1 = (ty8 == 0) ? 6 : 31;
            if (tid == 0) {
                sm.it.rowsrc[0] = g_binstart[cb][r0 * NBP];
                sm.it.rowoff[0] = g_binstart[cb][(r1 + 1) * NBP];
            }
            __syncthreads();
            int s0 = sm.it.rowsrc[0], e0 = sm.it.rowoff[0];
            ncand = e0 - s0;
            if (ncand <= CAP) {
                for (int i = tid; i < ncand; i += 256) {
                    float4 p = g_sorted[cb][s0 + i];
                    p.w = __uint_as_float((unsigned)(s0 + i));
                    sm.it.cand[i] = p;
                }
            }
            margin = (ty8 == 0) ? (7.0f * H_BIN - gth) : (gth - 25.0f * H_BIN);
            sk_t0 = r0; sk_t1 = r1; sk_p0 = 0; sk_p1 = NBP - 1;
        } else {
            int ht0 = max(bt0 - 2, 0), ht1 = min(bt0 + 5, NBT - 1);
            int hp0 = max(bp0 - 2, 0), hp1 = min(bp0 + 5, NBP - 1);
            int nrows = ht1 - ht0 + 1;
            if (tid < nrows) {
                int s = g_binstart[cb][(ht0 + tid) * NBP + hp0];
                int e = g_binstart[cb][(ht0 + tid) * NBP + hp1 + 1];
                sm.it.rowsrc[tid] = s;
                sm.it.rowoff[tid] = e - s;
            }
            __syncthreads();
            if (tid == 0) {
                int off = 0;
                for (int r = 0; r < nrows; ++r) {
                    int len = sm.it.rowoff[r];
                    sm.it.rowoff[r] = off;
                    off += len;
                }
                sm.it.rowoff[nrows] = off;
            }
            __syncthreads();
            ncand = sm.it.rowoff[nrows];
            if (ncand <= CAP) {
                for (int r = 0; r < nrows; ++r) {
                    int o0 = sm.it.rowoff[r], len = sm.it.rowoff[r + 1] - o0, s0 = sm.it.rowsrc[r];
                    for (int i = tid; i < len; i += 256) {
                        float4 p = g_sorted[cb][s0 + i];
                        p.w = __uint_as_float((unsigned)(s0 + i));
                        sm.it.cand[o0 + i] = p;
                    }
                }
            }
            float mT = (ht0 > 0)       ? (gth - (float)ht0 * H_BIN)            : 1e9f;
            float mB = (ht1 < NBT - 1) ? ((float)(ht1 + 1) * H_BIN - gth)      : 1e9f;
            float gpp = gph + PI_F;
            float mL = (hp0 > 0)       ? (gpp - (float)hp0 * H_BIN)            : 1e9f;
            float mR = (hp1 < NBP - 1) ? ((float)(hp1 + 1) * H_BIN - gpp)      : 1e9f;
            margin = fminf(fminf(mT, mB), fminf(mL, mR));
            sk_t0 = ht0; sk_t1 = ht1; sk_p0 = hp0; sk_p1 = hp1;
        }
        __syncthreads();

        bool ovf = ncand > CAP;
        unsigned k0 = KINF, k1 = KINF, k2 = KINF;

        if (!ovf) {
#pragma unroll 4
            for (int i = 0; i < ncand; ++i) {
                float4 p = sm.it.cand[i];
                float dx = gth - p.x, dy = gph - p.y;
                float d = fmaf(dx, dx, dy * dy);
                unsigned key = (__float_as_uint(d) & 0xFFFFF800u) | __float_as_uint(p.w);
                ins3(k0, k1, k2, key);
            }
        }

        float d2k = __uint_as_float(k2 & 0xFFFFF800u);
        if (ovf || d2k > margin * margin) {
            int bt = min(irow >> 2, NBT - 1);
            int bp = min(icol >> 2, NBP - 1);
            int st0 = ovf ? 1000 : sk_t0, st1 = ovf ? -1 : sk_t1;
            int sp0 = ovf ? 1000 : sk_p0, sp1 = ovf ? -1 : sk_p1;
            for (int R = 0; R <= 64; ++R) {
                if (R > 0) {
                    float lb = (float)(R - 1) * H_BIN;
                    d2k = __uint_as_float(k2 & 0xFFFFF800u);
                    if (d2k <= lb * lb) break;
                }
                int t0 = max(bt - R, 0), t1 = min(bt + R, NBT - 1);
                int p0 = max(bp - R, 0), p1 = min(bp + R, NBP - 1);
                for (int y = t0; y <= t1; ++y) {
                    bool full = (R == 0) || (y == bt - R) || (y == bt + R);
                    int xs = full ? p0 : (bp - R);
                    int xe = full ? p1 : (bp + R);
                    int xstep = full ? 1 : (2 * R);
                    for (int x = xs; x <= xe; x += xstep) {
                        if (x < 0 || x > NBP - 1) continue;
                        if (y >= st0 && y <= st1 && x >= sp0 && x <= sp1) continue;
                        int bi = y * NBP + x;
                        int s0 = g_binstart[cb][bi], s1 = g_binstart[cb][bi + 1];
                        for (int i = s0; i < s1; ++i) {
                            float4 p = g_sorted[cb][i];
                            float dx = gth - p.x, dy = gph - p.y;
                            float d = fmaf(dx, dx, dy * dy);
                            unsigned key = (__float_as_uint(d) & 0xFFFFF800u) | (unsigned)i;
                            ins3(k0, k1, k2, key);
                        }
                    }
                }
            }
        }

        // recompute exact distances of winners; weights = d_k / sum(d)
        float4 q0 = g_sorted[cb][k0 & 0x7FFu];
        float4 q1 = g_sorted[cb][k1 & 0x7FFu];
        float4 q2 = g_sorted[cb][k2 & 0x7FFu];
        float dx, dy;
        dx = gth - q0.x; dy = gph - q0.y; float e0 = fmaf(dx, dx, dy * dy);
        dx = gth - q1.x; dy = gph - q1.y; float e1 = fmaf(dx, dx, dy * dy);
        dx = gth - q2.x; dy = gph - q2.y; float e2 = fmaf(dx, dx, dy * dy);
        float s = e0 + e1 + e2;
        g_grid[cb][irow * NLON + icol] = (e0 * q0.z + e1 * q1.z + e2 * q2.z) / s;
    }
    gbar(1);

    // ================= Phase C: DFT real part (block = grid row) ============
    {
        int combo = bid >> 7;
        int k     = bid & 127;
        sm.rx.row[tid]  = g_grid[combo][k * NLON + tid];
        sm.rx.ctab[tid] = cosf((2.0f * PI_F / NLON) * (float)tid);
        __syncthreads();
        for (int m = wid; m < MMAX; m += 8) {
            float acc = 0.0f;
#pragma unroll
            for (int j = 0; j < 8; ++j) {
                int n = lane + 32 * j;
                acc = fmaf(sm.rx.row[n], sm.rx.ctab[(m * n) & (NLON - 1)], acc);
            }
#pragma unroll
            for (int o = 16; o > 0; o >>= 1) acc += __shfl_down_sync(0xffffffffu, acc, o);
            if (lane == 0) g_rexf[combo][m][k] = acc * (2.0f * PI_F / NLON);
        }
    }
    gbar(2);

    // ================= Phase D: coefficients + partial loss =================
    {
        int gw0 = bid * 8 + wid;
        for (int task = gw0; task < NB * LMAX * MMAX; task += 4096) {
            int b = task / (LMAX * MMAX);
            int r = task % (LMAX * MMAX);
            int l = r / MMAX;
            int m = r % MMAX;
            const float* pw = g_pctw[m][l];
            const float* xp = g_rexf[b][m];
            const float* xt = g_rexf[2 + b][m];
            float pc = 0.0f, tc = 0.0f;
#pragma unroll
            for (int k = lane; k < NLAT; k += 32) {
                float w = pw[k];
                pc = fmaf(xp[k], w, pc);
                tc = fmaf(xt[k], w, tc);
            }
#pragma unroll
            for (int o = 16; o > 0; o >>= 1) {
                pc += __shfl_down_sync(0xffffffffu, pc, o);
                tc += __shfl_down_sync(0xffffffffu, tc, o);
            }
            if (lane == 0) {
                float d = pc - tc;
                float q = (float)(LMAX - 1 - l);
                g_part[task] = d * d * expf(-q * q / (2.0f * LMAX * LMAX));
            }
        }
    }

    // ================= Final: last block reduces (no 4th barrier) ===========
    __syncthreads();
    if (tid == 0) {
        __threadfence();
        int t = atomicAdd(&g_done, 1);
        s_last = (t == NBLK - 1) ? 1 : 0;
    }
    __syncthreads();
    if (s_last) {
        __threadfence();
        float acc = 0.0f;
        for (int i = tid; i < NB * LMAX * MMAX; i += 256) acc += g_part[i];
#pragma unroll
        for (int o = 16; o > 0; o >>= 1) acc += __shfl_down_sync(0xffffffffu, acc, o);
        if (lane == 0) sm.red[wid] = acc;
        __syncthreads();
        if (tid == 0) {
            float v = 0.0f;
            for (int j = 0; j < 8; ++j) v += sm.red[j];
            out[0] = v / (float)NB;
            g_done = 0;
            __threadfence();
        }
    }
}

extern "C" void kernel_launch(void* const* d_in, const int* in_sizes, int n_in,
                              void* d_out, int out_size) {
    const float* pred = (const float*)d_in[0];
    const float* tgt  = (const float*)d_in[1];
    k_mega<<<NBLK, 256>>>(pred, tgt, (float*)d_out);
}